// round 3
// baseline (speedup 1.0000x reference)
#include <cuda_runtime.h>

// Problem dims
#define NB 128   // batch
#define NI 256   // in_features
#define NH 128   // H
#define NO 32    // OUT

#define BT   32   // b per CTA (kernel A)
#define DROW 260  // padded d-row stride in floats (float4 loads hit 4-phase floor)

// Scratch: w[h][b][o]  (fully overwritten every launch -> no init needed)
__device__ float g_w[NH * NB * NO];

__device__ __forceinline__ unsigned long long pack_dup(float v) {
    unsigned long long r;
    unsigned int b = __float_as_uint(v);
    asm("mov.b64 %0, {%1, %1};" : "=l"(r) : "r"(b));
    return r;
}

__device__ __forceinline__ void fma2(unsigned long long& a,
                                     unsigned long long t,
                                     unsigned long long d) {
    asm("fma.rn.f32x2 %0, %1, %2, %3;" : "=l"(a) : "l"(t), "l"(d), "l"(a));
}

// ---------------------------------------------------------------------------
// Kernel A: per (h, b-tile) CTA.
//   Ts[i][o] = sigma_psi[i,h,o]^2          (smem, 32 KB, broadcast reads)
//   dS[bl][i] = (chi[i,h] - x[b0+bl,i])^2  (smem, padded rows)
//   s[b][o]  = sum_i Ts[i][o] * dS[b][i]   (f32x2 packed FMA, lane<->b)
//   g_w[h][b][o] = 1 / (s + sigma_eps[h,o]^2)
// ---------------------------------------------------------------------------
__global__ __launch_bounds__(128, 3) void order1_main(
    const float* __restrict__ input,      // [NB][NI]
    const float* __restrict__ sigma_psi,  // [NI][NH][NO]
    const float* __restrict__ chi,        // [NI][NH]
    const float* __restrict__ sigma_eps)  // [NH][NO]
{
    extern __shared__ float smem[];
    float* Ts = smem;            // [NI][NO]  = 8192 floats
    float* dS = smem + NI * NO;  // [BT][DROW]

    const int h   = blockIdx.y;
    const int b0  = blockIdx.x * BT;
    const int tid = threadIdx.x;

    // Phase 1: load + square sigma_psi slice for this h (coalesced over o)
    for (int idx = tid; idx < NI * NO; idx += 128) {
        const int i = idx >> 5;
        const int o = idx & 31;
        float v = sigma_psi[i * (NH * NO) + h * NO + o];
        Ts[idx] = v * v;
    }

    // Phase 2: build d = (chi - x)^2 for the 32 b's of this tile
    for (int i = tid; i < NI; i += 128) {
        const float cv = chi[i * NH + h];
#pragma unroll
        for (int bl = 0; bl < BT; bl++) {
            float xv = input[(b0 + bl) * NI + i];
            float df = cv - xv;
            dS[bl * DROW + i] = df * df;  // bank = (4*bl + i) % 32: conflict-free
        }
    }
    __syncthreads();

    // Phase 3: lane = local b, warp owns 8 consecutive o's, acc packed f32x2
    const int w    = tid >> 5;
    const int lane = tid & 31;
    const float* dRow = dS + lane * DROW;
    const float* Tcol = Ts + w * 8;

    unsigned long long acc0 = 0ull, acc1 = 0ull, acc2 = 0ull, acc3 = 0ull;

#pragma unroll 4
    for (int i = 0; i < NI; i += 4) {
        float4 d4 = *reinterpret_cast<const float4*>(dRow + i);
        float dv0 = d4.x, dv1 = d4.y, dv2 = d4.z, dv3 = d4.w;
#pragma unroll
        for (int r = 0; r < 4; r++) {
            float dvr = (r == 0) ? dv0 : (r == 1) ? dv1 : (r == 2) ? dv2 : dv3;
            unsigned long long dd = pack_dup(dvr);
            // warp-uniform (broadcast) T loads: 8 o's = 2x 16B
            ulonglong2 ta = *reinterpret_cast<const ulonglong2*>(Tcol + (i + r) * NO);
            ulonglong2 tb = *reinterpret_cast<const ulonglong2*>(Tcol + (i + r) * NO + 4);
            fma2(acc0, ta.x, dd);
            fma2(acc1, ta.y, dd);
            fma2(acc2, tb.x, dd);
            fma2(acc3, tb.y, dd);
        }
    }

    // Epilogue: w = 1/(s + eps^2), store to g_w[h][b][o]
    const int b = b0 + lane;
    unsigned long long accs[4] = {acc0, acc1, acc2, acc3};
    float wv[8];
#pragma unroll
    for (int p = 0; p < 4; p++) {
        unsigned int lo, hi;
        asm("mov.b64 {%0, %1}, %2;" : "=r"(lo), "=r"(hi) : "l"(accs[p]));
        float s0 = __uint_as_float(lo);
        float s1 = __uint_as_float(hi);
        const int o = w * 8 + 2 * p;
        float e0 = sigma_eps[h * NO + o];
        float e1 = sigma_eps[h * NO + o + 1];
        wv[2 * p]     = __fdividef(1.0f, fmaf(e0, e0, s0));
        wv[2 * p + 1] = __fdividef(1.0f, fmaf(e1, e1, s1));
    }
    float* gp = g_w + (h * NB + b) * NO + w * 8;
    *reinterpret_cast<float4*>(gp)     = make_float4(wv[0], wv[1], wv[2], wv[3]);
    *reinterpret_cast<float4*>(gp + 4) = make_float4(wv[4], wv[5], wv[6], wv[7]);
}

// ---------------------------------------------------------------------------
// Kernel B: reduce over h, apply prior, write post_mu and post_sigma2
// ---------------------------------------------------------------------------
__global__ __launch_bounds__(128) void order1_finish(
    const float* __restrict__ eta,        // [NH][NO]
    const float* __restrict__ mu_phi,     // [NO]
    const float* __restrict__ sigma_phi,  // [NO]
    float* __restrict__ out, int out_size)
{
    __shared__ float rsw[128];
    __shared__ float rswe[128];

    const int b = blockIdx.x;
    const int t = threadIdx.x;
    const int o = t & 31;
    const int g = t >> 5;

    float sw = 0.0f, swe = 0.0f;
    for (int h = g; h < NH; h += 4) {
        float wv = g_w[(h * NB + b) * NO + o];
        sw  += wv;
        swe += wv * eta[h * NO + o];
    }
    rsw[t]  = sw;
    rswe[t] = swe;
    __syncthreads();

    if (g == 0) {
        sw  += rsw[o + 32] + rsw[o + 64] + rsw[o + 96];
        swe += rswe[o + 32] + rswe[o + 64] + rswe[o + 96];
        float sp  = sigma_phi[o];
        float sp2 = sp * sp;
        float denom = fmaf(sp2, sw, 1.0f);
        float inv   = 1.0f / denom;
        out[b * NO + o] = (mu_phi[o] + sp2 * swe) * inv;
        if (out_size >= 2 * NB * NO)
            out[NB * NO + b * NO + o] = sp2 * inv;
    }
}

extern "C" void kernel_launch(void* const* d_in, const int* in_sizes, int n_in,
                              void* d_out, int out_size) {
    const float* input     = (const float*)d_in[0];
    const float* sigma_psi = (const float*)d_in[1];
    const float* chi       = (const float*)d_in[2];
    const float* sigma_eps = (const float*)d_in[3];
    const float* eta       = (const float*)d_in[4];
    const float* mu_phi    = (const float*)d_in[5];
    const float* sigma_phi = (const float*)d_in[6];

    const int smemA = (NI * NO + BT * DROW) * (int)sizeof(float);  // 66048 B
    cudaFuncSetAttribute(order1_main,
                         cudaFuncAttributeMaxDynamicSharedMemorySize, smemA);

    dim3 gridA(NB / BT, NH);  // (4, 128) = 512 CTAs
    order1_main<<<gridA, 128, smemA>>>(input, sigma_psi, chi, sigma_eps);
    order1_finish<<<NB, 128>>>(eta, mu_phi, sigma_phi, (float*)d_out, out_size);
}

// round 4
// speedup vs baseline: 1.1745x; 1.1745x over previous
#include <cuda_runtime.h>

// Problem dims
#define NB 128   // batch
#define NI 256   // in_features
#define NH 128   // H
#define NO 32    // OUT

#define BT   32   // b per CTA (kernel A)
#define DROW 260  // padded d-row stride in floats (float4 loads hit 4-phase floor)

// Scratch: w[b][h][o]  (fully overwritten every launch -> no init needed)
__device__ float g_w[NB * NH * NO];

__device__ __forceinline__ unsigned long long pack_dup(float v) {
    unsigned long long r;
    unsigned int b = __float_as_uint(v);
    asm("mov.b64 %0, {%1, %1};" : "=l"(r) : "r"(b));
    return r;
}

__device__ __forceinline__ void fma2(unsigned long long& a,
                                     unsigned long long t,
                                     unsigned long long d) {
    asm("fma.rn.f32x2 %0, %1, %2, %3;" : "=l"(a) : "l"(t), "l"(d), "l"(a));
}

// ---------------------------------------------------------------------------
// Kernel A: per (h, b-tile) CTA, 256 threads (8 warps).
//   Warp w: o-group = w&3 (8 outputs), i-half = w>>2 (128 i each).
//   Ts[i][o]  = sigma_psi[i,h,o]^2          (smem, broadcast reads)
//   dS[bl][i] = (chi[i,h] - x[b0+bl,i])^2   (smem, padded rows)
//   s[b][o]   = sum_i Ts[i][o] * dS[b][i]   (f32x2 packed FMA, lane<->b)
//   g_w[b][h][o] = 1 / (s + sigma_eps[h,o]^2)
// ---------------------------------------------------------------------------
__global__ __launch_bounds__(256, 3) void order1_main(
    const float* __restrict__ input,      // [NB][NI]
    const float* __restrict__ sigma_psi,  // [NI][NH][NO]
    const float* __restrict__ chi,        // [NI][NH]
    const float* __restrict__ sigma_eps)  // [NH][NO]
{
    extern __shared__ float smem[];
    float* Ts = smem;                              // [NI][NO] = 8192 floats
    float* dS = smem + NI * NO;                    // [BT][DROW] = 8320 floats
    unsigned long long* P =                        // [4][32][4] u64 partials
        reinterpret_cast<unsigned long long*>(smem + NI * NO + BT * DROW);

    const int h   = blockIdx.y;
    const int b0  = blockIdx.x * BT;
    const int tid = threadIdx.x;

    // Phase 1: load + square sigma_psi slice for this h (float4, coalesced)
    {
        const float4* sp4 = reinterpret_cast<const float4*>(sigma_psi);
        float4* Ts4 = reinterpret_cast<float4*>(Ts);
#pragma unroll
        for (int k = 0; k < 8; k++) {
            int idx4 = tid + k * 256;          // 0..2047
            int i  = idx4 >> 3;
            int o4 = idx4 & 7;
            float4 v = sp4[(i * NH + h) * 8 + o4];
            v.x *= v.x; v.y *= v.y; v.z *= v.z; v.w *= v.w;
            Ts4[idx4] = v;
        }
    }

    // Phase 2: build d = (chi - x)^2 for the 32 b's of this tile (i = tid)
    {
        const int i = tid;
        const float cv = chi[i * NH + h];
#pragma unroll
        for (int bl = 0; bl < BT; bl++) {
            float xv = input[(b0 + bl) * NI + i];
            float df = cv - xv;
            dS[bl * DROW + i] = df * df;   // bank (4*bl + i) % 32: conflict-free
        }
    }
    __syncthreads();

    // Phase 3: lane = local b; warp owns 8 o's and one i-half of 128
    const int w    = tid >> 5;
    const int lane = tid & 31;
    const int og   = w & 3;        // o-group
    const int half = w >> 2;       // i-half
    const int i0   = half * 128;

    const float* dRow = dS + lane * DROW;
    const float* Tcol = Ts + og * 8;

    unsigned long long acc0 = 0ull, acc1 = 0ull, acc2 = 0ull, acc3 = 0ull;

#pragma unroll 4
    for (int i = i0; i < i0 + 128; i += 4) {
        float4 d4 = *reinterpret_cast<const float4*>(dRow + i);
#pragma unroll
        for (int r = 0; r < 4; r++) {
            float dvr = (r == 0) ? d4.x : (r == 1) ? d4.y : (r == 2) ? d4.z : d4.w;
            unsigned long long dd = pack_dup(dvr);
            // warp-uniform (broadcast) T loads: 8 o's = 2x 16B
            ulonglong2 ta = *reinterpret_cast<const ulonglong2*>(Tcol + (i + r) * NO);
            ulonglong2 tb = *reinterpret_cast<const ulonglong2*>(Tcol + (i + r) * NO + 4);
            fma2(acc0, ta.x, dd);
            fma2(acc1, ta.y, dd);
            fma2(acc2, tb.x, dd);
            fma2(acc3, tb.y, dd);
        }
    }

    // Combine i-halves: upper-half warps publish partials through smem
    if (half == 1) {
        ulonglong2* p2 = reinterpret_cast<ulonglong2*>(P + (og * 32 + lane) * 4);
        p2[0] = make_ulonglong2(acc0, acc1);
        p2[1] = make_ulonglong2(acc2, acc3);
    }
    __syncthreads();

    if (half == 0) {
        const ulonglong2* p2 =
            reinterpret_cast<const ulonglong2*>(P + (og * 32 + lane) * 4);
        ulonglong2 q0 = p2[0];
        ulonglong2 q1 = p2[1];
        unsigned long long mine[4]  = {acc0, acc1, acc2, acc3};
        unsigned long long other[4] = {q0.x, q0.y, q1.x, q1.y};

        const int b = b0 + lane;
        float wv[8];
#pragma unroll
        for (int p = 0; p < 4; p++) {
            unsigned int lo, hi, lo2, hi2;
            asm("mov.b64 {%0, %1}, %2;" : "=r"(lo), "=r"(hi) : "l"(mine[p]));
            asm("mov.b64 {%0, %1}, %2;" : "=r"(lo2), "=r"(hi2) : "l"(other[p]));
            float s0 = __uint_as_float(lo) + __uint_as_float(lo2);
            float s1 = __uint_as_float(hi) + __uint_as_float(hi2);
            const int o = og * 8 + 2 * p;
            float e0 = sigma_eps[h * NO + o];
            float e1 = sigma_eps[h * NO + o + 1];
            wv[2 * p]     = __fdividef(1.0f, fmaf(e0, e0, s0));
            wv[2 * p + 1] = __fdividef(1.0f, fmaf(e1, e1, s1));
        }
        // g_w layout: [b][h][o]  (finish kernel reads contiguously)
        float* gp = g_w + (b * NH + h) * NO + og * 8;
        *reinterpret_cast<float4*>(gp)     = make_float4(wv[0], wv[1], wv[2], wv[3]);
        *reinterpret_cast<float4*>(gp + 4) = make_float4(wv[4], wv[5], wv[6], wv[7]);
    }
}

// ---------------------------------------------------------------------------
// Kernel B: one CTA per b; coalesced float4 streaming over [NH][NO] row.
// ---------------------------------------------------------------------------
__device__ __forceinline__ float4 f4add(float4 a, float4 b) {
    return make_float4(a.x + b.x, a.y + b.y, a.z + b.z, a.w + b.w);
}

__global__ __launch_bounds__(256) void order1_finish(
    const float* __restrict__ eta,        // [NH][NO]
    const float* __restrict__ mu_phi,     // [NO]
    const float* __restrict__ sigma_phi,  // [NO]
    float* __restrict__ out, int out_size)
{
    __shared__ float4 sA[256];
    __shared__ float4 sB[256];

    const int b = blockIdx.x;
    const int t = threadIdx.x;
    const int o4 = t & 7;    // which float4 within the 32-o block
    const int hg = t >> 3;   // h-group 0..31

    const float4* row  = reinterpret_cast<const float4*>(g_w + b * NH * NO);
    const float4* eta4 = reinterpret_cast<const float4*>(eta);

    float4 sw  = make_float4(0.f, 0.f, 0.f, 0.f);
    float4 swe = make_float4(0.f, 0.f, 0.f, 0.f);
#pragma unroll
    for (int k = 0; k < 4; k++) {
        int idx = (hg + 32 * k) * 8 + o4;   // coalesced across the warp
        float4 w4 = row[idx];
        float4 e4 = eta4[idx];
        sw = f4add(sw, w4);
        swe.x += w4.x * e4.x; swe.y += w4.y * e4.y;
        swe.z += w4.z * e4.z; swe.w += w4.w * e4.w;
    }
    sA[t] = sw;
    sB[t] = swe;
    __syncthreads();

#pragma unroll
    for (int s = 128; s >= 8; s >>= 1) {
        if (t < s) {
            sA[t] = f4add(sA[t], sA[t + s]);
            sB[t] = f4add(sB[t], sB[t + s]);
        }
        __syncthreads();
    }

    if (t < 8) {
        const int o = t * 4;
        float4 sws  = sA[t];
        float4 swes = sB[t];
        float4 mp = *reinterpret_cast<const float4*>(mu_phi + o);
        float4 sp = *reinterpret_cast<const float4*>(sigma_phi + o);

        float pm[4], ps[4];
        float swa[4]  = {sws.x, sws.y, sws.z, sws.w};
        float swea[4] = {swes.x, swes.y, swes.z, swes.w};
        float mpa[4]  = {mp.x, mp.y, mp.z, mp.w};
        float spa[4]  = {sp.x, sp.y, sp.z, sp.w};
#pragma unroll
        for (int c = 0; c < 4; c++) {
            float sp2 = spa[c] * spa[c];
            float inv = __fdividef(1.0f, fmaf(sp2, swa[c], 1.0f));
            pm[c] = (mpa[c] + sp2 * swea[c]) * inv;
            ps[c] = sp2 * inv;
        }
        *reinterpret_cast<float4*>(out + b * NO + o) =
            make_float4(pm[0], pm[1], pm[2], pm[3]);
        if (out_size >= 2 * NB * NO)
            *reinterpret_cast<float4*>(out + NB * NO + b * NO + o) =
                make_float4(ps[0], ps[1], ps[2], ps[3]);
    }
}

extern "C" void kernel_launch(void* const* d_in, const int* in_sizes, int n_in,
                              void* d_out, int out_size) {
    const float* input     = (const float*)d_in[0];
    const float* sigma_psi = (const float*)d_in[1];
    const float* chi       = (const float*)d_in[2];
    const float* sigma_eps = (const float*)d_in[3];
    const float* eta       = (const float*)d_in[4];
    const float* mu_phi    = (const float*)d_in[5];
    const float* sigma_phi = (const float*)d_in[6];

    // Ts + dS + P partials
    const int smemA =
        (NI * NO + BT * DROW) * (int)sizeof(float) + 4 * 32 * 4 * 8;  // 70144 B
    cudaFuncSetAttribute(order1_main,
                         cudaFuncAttributeMaxDynamicSharedMemorySize, smemA);

    dim3 gridA(NB / BT, NH);  // (4, 128) = 512 CTAs
    order1_main<<<gridA, 256, smemA>>>(input, sigma_psi, chi, sigma_eps);
    order1_finish<<<NB, 256>>>(eta, mu_phi, sigma_phi, (float*)d_out, out_size);
}

// round 5
// speedup vs baseline: 1.3034x; 1.1098x over previous
#include <cuda_runtime.h>

// Problem dims
#define NB 128   // batch
#define NI 256   // in_features
#define NH 128   // H
#define NO 32    // OUT

#define DROW 260  // padded d-row stride in floats

// Scratch: w[b][h][o]  (fully overwritten every launch -> no init needed)
__device__ float g_w[NB * NH * NO];

__device__ __forceinline__ unsigned long long pack_dup(float v) {
    unsigned long long r;
    unsigned int b = __float_as_uint(v);
    asm("mov.b64 %0, {%1, %1};" : "=l"(r) : "r"(b));
    return r;
}

__device__ __forceinline__ void fma2(unsigned long long& a,
                                     unsigned long long t,
                                     unsigned long long d) {
    asm("fma.rn.f32x2 %0, %1, %2, %3;" : "=l"(a) : "l"(t), "l"(d), "l"(a));
}

// Profile-position pads: shift ncu -s 5 -c 1 onto order1_main (launch #6).
__global__ void profile_pad_a() {}
__global__ void profile_pad_b() {}

// ---------------------------------------------------------------------------
// Kernel A: ONE CTA per h, 128 threads (4 warps = 4 o-groups).
//   Lane = b (mod 32); each lane carries R=4 b-strips (b, b+32, b+64, b+96)
//   in registers so each T-broadcast (the expensive crossbar op) feeds
//   128 b x 8 o = 1024 MACs -> ~85 MACs per crossbar-cycle (was 28).
//   Ts[i][o]  = sigma_psi[i,h,o]^2          (smem, broadcast reads)
//   dS[b][i]  = (chi[i,h] - x[b,i])^2       (smem, padded rows, ALL 128 b)
//   g_w[b][h][o] = 1 / (s + sigma_eps[h,o]^2)
// ---------------------------------------------------------------------------
__global__ __launch_bounds__(128, 1) void order1_main(
    const float* __restrict__ input,      // [NB][NI]
    const float* __restrict__ sigma_psi,  // [NI][NH][NO]
    const float* __restrict__ chi,        // [NI][NH]
    const float* __restrict__ sigma_eps)  // [NH][NO]
{
    extern __shared__ float smem[];
    float* Ts = smem;            // [NI][NO]   = 8192 floats
    float* dS = smem + NI * NO;  // [NB][DROW] = 33280 floats

    const int h   = blockIdx.x;
    const int tid = threadIdx.x;

    // Phase 1: load + square sigma_psi slice for this h (float4, coalesced)
    {
        const float4* sp4 = reinterpret_cast<const float4*>(sigma_psi);
        float4* Ts4 = reinterpret_cast<float4*>(Ts);
#pragma unroll
        for (int k = 0; k < 16; k++) {
            int idx4 = tid + k * 128;          // 0..2047
            int i  = idx4 >> 3;
            int o4 = idx4 & 7;
            float4 v = sp4[(i * NH + h) * 8 + o4];
            v.x *= v.x; v.y *= v.y; v.z *= v.z; v.w *= v.w;
            Ts4[idx4] = v;
        }
    }

    // Phase 2: build dS = (chi - x)^2 for ALL 128 b (float4 over i)
    {
        const int iq = tid & 63;          // i-quad: i = 4*iq .. 4*iq+3
        const int i  = iq * 4;
        const float c0 = chi[(i + 0) * NH + h];
        const float c1 = chi[(i + 1) * NH + h];
        const float c2 = chi[(i + 2) * NH + h];
        const float c3 = chi[(i + 3) * NH + h];
#pragma unroll 4
        for (int k = 0; k < 64; k++) {
            const int b = (tid >> 6) + 2 * k;   // covers 0..127 across thread halves
            float4 x4 = *reinterpret_cast<const float4*>(input + b * NI + i);
            float4 d4;
            d4.x = (c0 - x4.x) * (c0 - x4.x);
            d4.y = (c1 - x4.y) * (c1 - x4.y);
            d4.z = (c2 - x4.z) * (c2 - x4.z);
            d4.w = (c3 - x4.w) * (c3 - x4.w);
            *reinterpret_cast<float4*>(dS + b * DROW + i) = d4;
        }
    }
    __syncthreads();

    // Phase 3: warp = o-group (8 o's); lane carries 4 b-strips in registers.
    const int og   = tid >> 5;   // 0..3
    const int lane = tid & 31;
    const float* Tcol = Ts + og * 8;

    // acc[strip][opair]
    unsigned long long acc[4][4];
#pragma unroll
    for (int r = 0; r < 4; r++)
#pragma unroll
        for (int p = 0; p < 4; p++) acc[r][p] = 0ull;

    const float* dR0 = dS + (lane      ) * DROW;
    const float* dR1 = dS + (lane + 32 ) * DROW;
    const float* dR2 = dS + (lane + 64 ) * DROW;
    const float* dR3 = dS + (lane + 96 ) * DROW;

#pragma unroll 2
    for (int i = 0; i < NI; i += 4) {
        float4 dv0 = *reinterpret_cast<const float4*>(dR0 + i);
        float4 dv1 = *reinterpret_cast<const float4*>(dR1 + i);
        float4 dv2 = *reinterpret_cast<const float4*>(dR2 + i);
        float4 dv3 = *reinterpret_cast<const float4*>(dR3 + i);
#pragma unroll
        for (int rr = 0; rr < 4; rr++) {
            // T broadcast: 8 o's for this i (2x LDS.128, warp-uniform)
            ulonglong2 ta = *reinterpret_cast<const ulonglong2*>(Tcol + (i + rr) * NO);
            ulonglong2 tb = *reinterpret_cast<const ulonglong2*>(Tcol + (i + rr) * NO + 4);
            float f0 = (rr == 0) ? dv0.x : (rr == 1) ? dv0.y : (rr == 2) ? dv0.z : dv0.w;
            float f1 = (rr == 0) ? dv1.x : (rr == 1) ? dv1.y : (rr == 2) ? dv1.z : dv1.w;
            float f2 = (rr == 0) ? dv2.x : (rr == 1) ? dv2.y : (rr == 2) ? dv2.z : dv2.w;
            float f3 = (rr == 0) ? dv3.x : (rr == 1) ? dv3.y : (rr == 2) ? dv3.z : dv3.w;
            unsigned long long dd0 = pack_dup(f0);
            unsigned long long dd1 = pack_dup(f1);
            unsigned long long dd2 = pack_dup(f2);
            unsigned long long dd3 = pack_dup(f3);
            fma2(acc[0][0], ta.x, dd0); fma2(acc[0][1], ta.y, dd0);
            fma2(acc[0][2], tb.x, dd0); fma2(acc[0][3], tb.y, dd0);
            fma2(acc[1][0], ta.x, dd1); fma2(acc[1][1], ta.y, dd1);
            fma2(acc[1][2], tb.x, dd1); fma2(acc[1][3], tb.y, dd1);
            fma2(acc[2][0], ta.x, dd2); fma2(acc[2][1], ta.y, dd2);
            fma2(acc[2][2], tb.x, dd2); fma2(acc[2][3], tb.y, dd2);
            fma2(acc[3][0], ta.x, dd3); fma2(acc[3][1], ta.y, dd3);
            fma2(acc[3][2], tb.x, dd3); fma2(acc[3][3], tb.y, dd3);
        }
    }

    // Epilogue: w = 1/(s + eps^2) for 4 strips x 8 o per lane
    float ev[8];
#pragma unroll
    for (int k = 0; k < 8; k++) {
        float e = sigma_eps[h * NO + og * 8 + k];
        ev[k] = e * e;
    }
#pragma unroll
    for (int r = 0; r < 4; r++) {
        const int b = r * 32 + lane;
        float wv[8];
#pragma unroll
        for (int p = 0; p < 4; p++) {
            unsigned int lo, hi;
            asm("mov.b64 {%0, %1}, %2;" : "=r"(lo), "=r"(hi) : "l"(acc[r][p]));
            wv[2 * p]     = __fdividef(1.0f, __uint_as_float(lo) + ev[2 * p]);
            wv[2 * p + 1] = __fdividef(1.0f, __uint_as_float(hi) + ev[2 * p + 1]);
        }
        float* gp = g_w + (b * NH + h) * NO + og * 8;  // [b][h][o]
        *reinterpret_cast<float4*>(gp)     = make_float4(wv[0], wv[1], wv[2], wv[3]);
        *reinterpret_cast<float4*>(gp + 4) = make_float4(wv[4], wv[5], wv[6], wv[7]);
    }
}

// ---------------------------------------------------------------------------
// Kernel B: CTA = (b, o-group of 8). 512 CTAs x 256 threads.
//   thread t: h = t>>1, q = t&1 (which float4 of the o-group).
//   Warp-shuffle reduction over h, tiny smem combine.
// ---------------------------------------------------------------------------
__global__ __launch_bounds__(256) void order1_finish(
    const float* __restrict__ eta,        // [NH][NO]
    const float* __restrict__ mu_phi,     // [NO]
    const float* __restrict__ sigma_phi,  // [NO]
    float* __restrict__ out, int out_size)
{
    __shared__ float4 sA[16];
    __shared__ float4 sB[16];

    const int b  = blockIdx.x >> 2;
    const int og = blockIdx.x & 3;
    const int t  = threadIdx.x;
    const int h  = t >> 1;
    const int q  = t & 1;
    const int wid = t >> 5;

    const float4* row4 = reinterpret_cast<const float4*>(g_w + b * NH * NO);
    const float4* eta4 = reinterpret_cast<const float4*>(eta);

    const int idx = h * 8 + og * 2 + q;
    float4 w4 = row4[idx];
    float4 e4 = eta4[idx];
    float4 sw  = w4;
    float4 swe = make_float4(w4.x * e4.x, w4.y * e4.y, w4.z * e4.z, w4.w * e4.w);

    // reduce over h within warp (lanes differing in bits 1..4 share q)
#pragma unroll
    for (int m = 2; m <= 16; m <<= 1) {
        sw.x += __shfl_xor_sync(0xffffffffu, sw.x, m);
        sw.y += __shfl_xor_sync(0xffffffffu, sw.y, m);
        sw.z += __shfl_xor_sync(0xffffffffu, sw.z, m);
        sw.w += __shfl_xor_sync(0xffffffffu, sw.w, m);
        swe.x += __shfl_xor_sync(0xffffffffu, swe.x, m);
        swe.y += __shfl_xor_sync(0xffffffffu, swe.y, m);
        swe.z += __shfl_xor_sync(0xffffffffu, swe.z, m);
        swe.w += __shfl_xor_sync(0xffffffffu, swe.w, m);
    }
    if ((t & 31) < 2) {   // lanes 0 (q=0) and 1 (q=1) hold warp partials
        sA[wid * 2 + q] = sw;
        sB[wid * 2 + q] = swe;
    }
    __syncthreads();

    if (t < 2) {
        float4 a = sA[q], bb = sB[q];
#pragma unroll
        for (int k = 1; k < 8; k++) {
            float4 a2 = sA[k * 2 + q], b2 = sB[k * 2 + q];
            a.x += a2.x; a.y += a2.y; a.z += a2.z; a.w += a2.w;
            bb.x += b2.x; bb.y += b2.y; bb.z += b2.z; bb.w += b2.w;
        }
        const int o = og * 8 + q * 4;
        float4 mp = *reinterpret_cast<const float4*>(mu_phi + o);
        float4 sp = *reinterpret_cast<const float4*>(sigma_phi + o);
        float swa[4]  = {a.x, a.y, a.z, a.w};
        float swea[4] = {bb.x, bb.y, bb.z, bb.w};
        float mpa[4]  = {mp.x, mp.y, mp.z, mp.w};
        float spa[4]  = {sp.x, sp.y, sp.z, sp.w};
        float pm[4], ps[4];
#pragma unroll
        for (int c = 0; c < 4; c++) {
            float sp2 = spa[c] * spa[c];
            float inv = __fdividef(1.0f, fmaf(sp2, swa[c], 1.0f));
            pm[c] = (mpa[c] + sp2 * swea[c]) * inv;
            ps[c] = sp2 * inv;
        }
        *reinterpret_cast<float4*>(out + b * NO + o) =
            make_float4(pm[0], pm[1], pm[2], pm[3]);
        if (out_size >= 2 * NB * NO)
            *reinterpret_cast<float4*>(out + NB * NO + b * NO + o) =
                make_float4(ps[0], ps[1], ps[2], ps[3]);
    }
}

extern "C" void kernel_launch(void* const* d_in, const int* in_sizes, int n_in,
                              void* d_out, int out_size) {
    const float* input     = (const float*)d_in[0];
    const float* sigma_psi = (const float*)d_in[1];
    const float* chi       = (const float*)d_in[2];
    const float* sigma_eps = (const float*)d_in[3];
    const float* eta       = (const float*)d_in[4];
    const float* mu_phi    = (const float*)d_in[5];
    const float* sigma_phi = (const float*)d_in[6];

    const int smemA = (NI * NO + NB * DROW) * (int)sizeof(float);  // 165888 B
    cudaFuncSetAttribute(order1_main,
                         cudaFuncAttributeMaxDynamicSharedMemorySize, smemA);

    // Launch pattern [pad, main, pad, finish]: puts order1_main at global
    // launch position 6 so ncu (-s 5 -c 1) finally profiles it.
    profile_pad_a<<<1, 32>>>();
    order1_main<<<NH, 128, smemA>>>(input, sigma_psi, chi, sigma_eps);
    profile_pad_b<<<1, 32>>>();
    order1_finish<<<NB * 4, 256>>>(eta, mu_phi, sigma_phi, (float*)d_out, out_size);
}

// round 6
// speedup vs baseline: 1.5489x; 1.1884x over previous
#include <cuda_runtime.h>

// Problem dims
#define NB 128   // batch
#define NI 256   // in_features
#define NH 128   // H
#define NO 32    // OUT

#define DROW 260  // padded d-row stride in floats (conflict-free strip reads)
#define PSTRIDE 18  // u64 stride for partial exchange (conflict-free)

// Scratch: w[b][h][o]  (fully overwritten every launch -> no init needed)
__device__ float g_w[NB * NH * NO];

__device__ __forceinline__ unsigned long long pack_dup(float v) {
    unsigned long long r;
    unsigned int b = __float_as_uint(v);
    asm("mov.b64 %0, {%1, %1};" : "=l"(r) : "r"(b));
    return r;
}

__device__ __forceinline__ void fma2(unsigned long long& a,
                                     unsigned long long t,
                                     unsigned long long d) {
    asm("fma.rn.f32x2 %0, %1, %2, %3;" : "=l"(a) : "l"(t), "l"(d), "l"(a));
}

// ---------------------------------------------------------------------------
// Kernel A: ONE CTA per h, 256 threads (8 warps = 4 o-groups x 2 i-halves).
//   Lane carries 4 b-strips (lane, +32, +64, +96) in registers so each
//   T-broadcast feeds 128 b x 8 o MACs. 2 warps/SMSP hide LDS/L2 latency.
// ---------------------------------------------------------------------------
__global__ __launch_bounds__(256, 1) void order1_main(
    const float* __restrict__ input,      // [NB][NI]
    const float* __restrict__ sigma_psi,  // [NI][NH][NO]
    const float* __restrict__ chi,        // [NI][NH]
    const float* __restrict__ sigma_eps)  // [NH][NO]
{
    extern __shared__ float smem[];
    float* Ts = smem;            // [NI][NO]   = 8192 floats
    float* dS = smem + NI * NO;  // [NB][DROW] = 33280 floats

    const int h   = blockIdx.x;
    const int tid = threadIdx.x;

    // Phase 1: load + square sigma_psi slice for this h (float4, coalesced)
    {
        const float4* sp4 = reinterpret_cast<const float4*>(sigma_psi);
        float4* Ts4 = reinterpret_cast<float4*>(Ts);
#pragma unroll
        for (int k = 0; k < 8; k++) {
            int idx4 = tid + k * 256;          // 0..2047
            int i  = idx4 >> 3;
            int o4 = idx4 & 7;
            float4 v = sp4[(i * NH + h) * 8 + o4];
            v.x *= v.x; v.y *= v.y; v.z *= v.z; v.w *= v.w;
            Ts4[idx4] = v;
        }
    }

    // Phase 2: dS[b][i] = (chi[i,h] - x[b,i])^2 for ALL 128 b.
    // Warp lanes share b; lanes = consecutive i-quads -> LDG and STS both
    // perfectly coalesced/conflict-free.
    {
        const int iq = tid & 63;   // i-quad
        const int bb = tid >> 6;   // 0..3 (uniform within warp)
        const int i  = iq * 4;
        const float c0 = chi[(i + 0) * NH + h];
        const float c1 = chi[(i + 1) * NH + h];
        const float c2 = chi[(i + 2) * NH + h];
        const float c3 = chi[(i + 3) * NH + h];
#pragma unroll 4
        for (int k = 0; k < 32; k++) {
            const int b = bb + 4 * k;
            float4 x4 = *reinterpret_cast<const float4*>(input + b * NI + i);
            float4 d4;
            d4.x = (c0 - x4.x) * (c0 - x4.x);
            d4.y = (c1 - x4.y) * (c1 - x4.y);
            d4.z = (c2 - x4.z) * (c2 - x4.z);
            d4.w = (c3 - x4.w) * (c3 - x4.w);
            *reinterpret_cast<float4*>(dS + b * DROW + i) = d4;
        }
    }
    __syncthreads();

    // Phase 3: warp = (og, half). 8 o's, 128 i's per warp.
    const int w    = tid >> 5;
    const int lane = tid & 31;
    const int og   = w & 3;
    const int half = w >> 2;
    const int i0   = half * 128;
    const float* Tcol = Ts + og * 8;

    unsigned long long acc[4][4];   // [b-strip][o-pair]
#pragma unroll
    for (int r = 0; r < 4; r++)
#pragma unroll
        for (int p = 0; p < 4; p++) acc[r][p] = 0ull;

    const float* dR0 = dS + (lane      ) * DROW;
    const float* dR1 = dS + (lane + 32 ) * DROW;
    const float* dR2 = dS + (lane + 64 ) * DROW;
    const float* dR3 = dS + (lane + 96 ) * DROW;

#pragma unroll 2
    for (int i = i0; i < i0 + 128; i += 4) {
        float4 dv0 = *reinterpret_cast<const float4*>(dR0 + i);
        float4 dv1 = *reinterpret_cast<const float4*>(dR1 + i);
        float4 dv2 = *reinterpret_cast<const float4*>(dR2 + i);
        float4 dv3 = *reinterpret_cast<const float4*>(dR3 + i);
#pragma unroll
        for (int rr = 0; rr < 4; rr++) {
            ulonglong2 ta = *reinterpret_cast<const ulonglong2*>(Tcol + (i + rr) * NO);
            ulonglong2 tb = *reinterpret_cast<const ulonglong2*>(Tcol + (i + rr) * NO + 4);
            float f0 = (rr == 0) ? dv0.x : (rr == 1) ? dv0.y : (rr == 2) ? dv0.z : dv0.w;
            float f1 = (rr == 0) ? dv1.x : (rr == 1) ? dv1.y : (rr == 2) ? dv1.z : dv1.w;
            float f2 = (rr == 0) ? dv2.x : (rr == 1) ? dv2.y : (rr == 2) ? dv2.z : dv2.w;
            float f3 = (rr == 0) ? dv3.x : (rr == 1) ? dv3.y : (rr == 2) ? dv3.z : dv3.w;
            unsigned long long dd0 = pack_dup(f0);
            unsigned long long dd1 = pack_dup(f1);
            unsigned long long dd2 = pack_dup(f2);
            unsigned long long dd3 = pack_dup(f3);
            fma2(acc[0][0], ta.x, dd0); fma2(acc[0][1], ta.y, dd0);
            fma2(acc[0][2], tb.x, dd0); fma2(acc[0][3], tb.y, dd0);
            fma2(acc[1][0], ta.x, dd1); fma2(acc[1][1], ta.y, dd1);
            fma2(acc[1][2], tb.x, dd1); fma2(acc[1][3], tb.y, dd1);
            fma2(acc[2][0], ta.x, dd2); fma2(acc[2][1], ta.y, dd2);
            fma2(acc[2][2], tb.x, dd2); fma2(acc[2][3], tb.y, dd2);
            fma2(acc[3][0], ta.x, dd3); fma2(acc[3][1], ta.y, dd3);
            fma2(acc[3][2], tb.x, dd3); fma2(acc[3][3], tb.y, dd3);
        }
    }

    // Exchange: half=1 publishes partials through smem (dS reused), then
    // half=0 combines, applies 1/(s+eps^2), stores g_w[b][h][o].
    __syncthreads();   // everyone done reading dS
    unsigned long long* P = reinterpret_cast<unsigned long long*>(dS);
    if (half == 1) {
        ulonglong2* p2 =
            reinterpret_cast<ulonglong2*>(P + (og * 32 + lane) * PSTRIDE);
#pragma unroll
        for (int k = 0; k < 8; k++)
            p2[k] = make_ulonglong2(acc[k >> 1][(k & 1) * 2],
                                    acc[k >> 1][(k & 1) * 2 + 1]);
    }
    __syncthreads();

    if (half == 0) {
        float ev[8];
#pragma unroll
        for (int k = 0; k < 8; k++) {
            float e = sigma_eps[h * NO + og * 8 + k];
            ev[k] = e * e;
        }
        const ulonglong2* p2 =
            reinterpret_cast<const ulonglong2*>(P + (og * 32 + lane) * PSTRIDE);
#pragma unroll
        for (int r = 0; r < 4; r++) {
            float wv[8];
#pragma unroll
            for (int q = 0; q < 4; q += 2) {
                ulonglong2 oth = p2[r * 2 + (q >> 1)];
                unsigned long long opair[2] = {oth.x, oth.y};
#pragma unroll
                for (int j = 0; j < 2; j++) {
                    unsigned int mlo, mhi, olo, ohi;
                    asm("mov.b64 {%0, %1}, %2;" : "=r"(mlo), "=r"(mhi) : "l"(acc[r][q + j]));
                    asm("mov.b64 {%0, %1}, %2;" : "=r"(olo), "=r"(ohi) : "l"(opair[j]));
                    float s0 = __uint_as_float(mlo) + __uint_as_float(olo);
                    float s1 = __uint_as_float(mhi) + __uint_as_float(ohi);
                    int oo = (q + j) * 2;
                    wv[oo]     = __fdividef(1.0f, s0 + ev[oo]);
                    wv[oo + 1] = __fdividef(1.0f, s1 + ev[oo + 1]);
                }
            }
            const int b = r * 32 + lane;
            float* gp = g_w + (b * NH + h) * NO + og * 8;   // [b][h][o]
            *reinterpret_cast<float4*>(gp)     = make_float4(wv[0], wv[1], wv[2], wv[3]);
            *reinterpret_cast<float4*>(gp + 4) = make_float4(wv[4], wv[5], wv[6], wv[7]);
        }
    }
}

// ---------------------------------------------------------------------------
// Kernel B: CTA per b, 512 threads. One coalesced float4 sweep of the 16KB
// g_w row + eta, butterfly h-reduction, tiny smem combine.
// ---------------------------------------------------------------------------
__global__ __launch_bounds__(512) void order1_finish(
    const float* __restrict__ eta,        // [NH][NO]
    const float* __restrict__ mu_phi,     // [NO]
    const float* __restrict__ sigma_phi,  // [NO]
    float* __restrict__ out, int out_size)
{
    __shared__ float4 sA[16 * 8];
    __shared__ float4 sB[16 * 8];

    const int b = blockIdx.x;
    const int t = threadIdx.x;
    const int wid = t >> 5;
    const int l = t & 31;

    const float4* row4 = reinterpret_cast<const float4*>(g_w + b * NH * NO);
    const float4* eta4 = reinterpret_cast<const float4*>(eta);

    float4 sw  = make_float4(0.f, 0.f, 0.f, 0.f);
    float4 swe = make_float4(0.f, 0.f, 0.f, 0.f);
#pragma unroll
    for (int rep = 0; rep < 2; rep++) {
        int idx = t + rep * 512;   // seg = idx&7 constant over rep
        float4 w4 = row4[idx];
        float4 e4 = eta4[idx];
        sw.x += w4.x; sw.y += w4.y; sw.z += w4.z; sw.w += w4.w;
        swe.x += w4.x * e4.x; swe.y += w4.y * e4.y;
        swe.z += w4.z * e4.z; swe.w += w4.w * e4.w;
    }

    // reduce over h bits within warp (lane bits 3,4), seg = lane&7 preserved
#pragma unroll
    for (int m = 8; m <= 16; m <<= 1) {
        sw.x += __shfl_xor_sync(0xffffffffu, sw.x, m);
        sw.y += __shfl_xor_sync(0xffffffffu, sw.y, m);
        sw.z += __shfl_xor_sync(0xffffffffu, sw.z, m);
        sw.w += __shfl_xor_sync(0xffffffffu, sw.w, m);
        swe.x += __shfl_xor_sync(0xffffffffu, swe.x, m);
        swe.y += __shfl_xor_sync(0xffffffffu, swe.y, m);
        swe.z += __shfl_xor_sync(0xffffffffu, swe.z, m);
        swe.w += __shfl_xor_sync(0xffffffffu, swe.w, m);
    }
    if (l < 8) {
        sA[wid * 8 + l] = sw;
        sB[wid * 8 + l] = swe;
    }
    __syncthreads();

    if (t < 8) {
        float4 a = sA[t], bb = sB[t];
#pragma unroll
        for (int k = 1; k < 16; k++) {
            float4 a2 = sA[k * 8 + t], b2 = sB[k * 8 + t];
            a.x += a2.x; a.y += a2.y; a.z += a2.z; a.w += a2.w;
            bb.x += b2.x; bb.y += b2.y; bb.z += b2.z; bb.w += b2.w;
        }
        const int o = t * 4;
        float4 mp = *reinterpret_cast<const float4*>(mu_phi + o);
        float4 sp = *reinterpret_cast<const float4*>(sigma_phi + o);
        float swa[4]  = {a.x, a.y, a.z, a.w};
        float swea[4] = {bb.x, bb.y, bb.z, bb.w};
        float mpa[4]  = {mp.x, mp.y, mp.z, mp.w};
        float spa[4]  = {sp.x, sp.y, sp.z, sp.w};
        float pm[4], ps[4];
#pragma unroll
        for (int c = 0; c < 4; c++) {
            float sp2 = spa[c] * spa[c];
            float inv = __fdividef(1.0f, fmaf(sp2, swa[c], 1.0f));
            pm[c] = (mpa[c] + sp2 * swea[c]) * inv;
            ps[c] = sp2 * inv;
        }
        *reinterpret_cast<float4*>(out + b * NO + o) =
            make_float4(pm[0], pm[1], pm[2], pm[3]);
        if (out_size >= 2 * NB * NO)
            *reinterpret_cast<float4*>(out + NB * NO + b * NO + o) =
                make_float4(ps[0], ps[1], ps[2], ps[3]);
    }
}

extern "C" void kernel_launch(void* const* d_in, const int* in_sizes, int n_in,
                              void* d_out, int out_size) {
    const float* input     = (const float*)d_in[0];
    const float* sigma_psi = (const float*)d_in[1];
    const float* chi       = (const float*)d_in[2];
    const float* sigma_eps = (const float*)d_in[3];
    const float* eta       = (const float*)d_in[4];
    const float* mu_phi    = (const float*)d_in[5];
    const float* sigma_phi = (const float*)d_in[6];

    const int smemA = (NI * NO + NB * DROW) * (int)sizeof(float);  // 165888 B
    cudaFuncSetAttribute(order1_main,
                         cudaFuncAttributeMaxDynamicSharedMemorySize, smemA);

    order1_main<<<NH, 256, smemA>>>(input, sigma_psi, chi, sigma_eps);
    order1_finish<<<NB, 512>>>(eta, mu_phi, sigma_phi, (float*)d_out, out_size);
}